// round 4
// baseline (speedup 1.0000x reference)
#include <cuda_runtime.h>
#include <math.h>

#define BB 2048
#define CC 3
#define TT 300
#define JJ 25
#define TJ (TT * JJ)            // 7500 elements per (b,c) slice
#define NSLICE (BB * CC)        // 6144 slices
#define HALF (TT / 2)           // 150 frames per half-warp
#define SPB 4                   // slices per block (each slice = 2 warps)
#define WPB (SPB * 2)           // 8 warps per block
#define NBLK (NSLICE / SPB)     // 1536 blocks
#define NTHREADS (WPB * 32)

// Global accumulators (allocation-free scratch). Zero-initialized at load;
// the last finishing block resets them -> deterministic across graph replays.
__device__ double g_rec = 0.0;
__device__ double g_smooth = 0.0;
__device__ unsigned int g_count = 0u;

__global__ void __launch_bounds__(NTHREADS, 8)
loss_kernel(const float* __restrict__ x, const float* __restrict__ tg,
            float* __restrict__ out) {
    const int warp = threadIdx.x >> 5;
    const int lane = threadIdx.x & 31;
    const int sidx = warp >> 1;                    // slice within block (0..3)
    const int half = warp & 1;                     // 0: t in [0,150)  1: [150,300)
    const int slice = blockIdx.x * SPB + sidx;     // < 6144

    const float* __restrict__ xs = x  + (size_t)slice * TJ;
    const float* __restrict__ ts = tg + (size_t)slice * TJ;

    const bool active = (lane < JJ);
    const int t0 = half * HALF;

    float accd = 0.0f;   // partial (sx - st) for joint j = lane over this half
    float rec  = 0.0f;   // sum of (x - t)^2 over this lane's elements

    #pragma unroll 5
    for (int tt = 0; tt < HALF; tt++) {
        const int t = t0 + tt;
        float xf = 0.0f, tf = 0.0f;
        if (active) {
            xf = __ldg(xs + t * JJ + lane);
            tf = __ldg(ts + t * JJ + lane);
        }
        const float d = xf - tf;
        rec = fmaf(d, d, rec);

        // element at global frame t contributes +x to sx if t < T-1,
        // and -x^2 if t > 0 (targets negated).
        float c = (t < TT - 1) ? d : 0.0f;
        if (t > 0) c -= (xf * xf - tf * tf);
        accd += c;
    }

    // rec: full warp shuffle reduce (all warps).
    #pragma unroll
    for (int o = 16; o > 0; o >>= 1)
        rec += __shfl_xor_sync(0xffffffffu, rec, o);

    __shared__ float s_accd[SPB][32];   // half-1 partial accd per slice
    __shared__ double s_rec[WPB];
    __shared__ double s_sm[SPB];

    if (lane == 0) s_rec[warp] = (double)rec;
    if (half == 1 && active) s_accd[sidx][lane] = accd;
    __syncthreads();

    if (half == 0) {
        float a = accd + (active ? s_accd[sidx][lane] : 0.0f);
        float av = (lane < JJ - 1) ? fabsf(a) : 0.0f;
        #pragma unroll
        for (int o = 16; o > 0; o >>= 1)
            av += __shfl_xor_sync(0xffffffffu, av, o);
        if (lane == 0) s_sm[sidx] = sqrt((double)av) / (double)TJ;
    }
    __syncthreads();

    if (threadIdx.x == 0) {
        double rtot = 0.0, stot = 0.0;
        #pragma unroll
        for (int w = 0; w < WPB; w++) rtot += s_rec[w];
        #pragma unroll
        for (int s = 0; s < SPB; s++) stot += s_sm[s];
        atomicAdd(&g_rec, rtot);
        atomicAdd(&g_smooth, stot);
        __threadfence();
        const unsigned int ticket = atomicAdd(&g_count, 1u);
        if (ticket == NBLK - 1) {
            const double rec_sum = atomicAdd(&g_rec, 0.0);
            const double sm_sum  = atomicAdd(&g_smooth, 0.0);
            const double rec_mean    = rec_sum / ((double)BB * CC * TT * JJ);
            const double smooth_mean = sm_sum  / ((double)BB * CC);
            out[0] = (float)(2.0 * rec_mean + 3.0 * smooth_mean);
            g_rec = 0.0;
            g_smooth = 0.0;
            __threadfence();
            g_count = 0u;
        }
    }
}

extern "C" void kernel_launch(void* const* d_in, const int* in_sizes, int n_in,
                              void* d_out, int out_size) {
    const float* x  = (const float*)d_in[0];
    const float* tg = (const float*)d_in[1];
    float* out = (float*)d_out;

    loss_kernel<<<NBLK, NTHREADS>>>(x, tg, out);
}

// round 6
// speedup vs baseline: 1.4229x; 1.4229x over previous
#include <cuda_runtime.h>
#include <math.h>

#define BB 2048
#define CC 3
#define TT 300
#define JJ 25
#define TJ (TT * JJ)            // 7500 elements per (b,c) slice
#define NSLICE (BB * CC)        // 6144 slices
#define WPB 8                   // warps per block (1 warp = 1 slice)
#define NBLK (NSLICE / WPB)     // 768 blocks
#define NTHREADS (WPB * 32)
#define NF4 (TJ / 4)            // 1875 float4 per slice (30000 B, 16B aligned)
#define KMAX (NF4 / JJ)         // 75 groups of 25 float4 (= 4 frames each)

// Global accumulators (allocation-free scratch). Zero-initialized at load;
// last finishing block resets them -> deterministic across graph replays.
__device__ double g_rec = 0.0;
__device__ double g_smooth = 0.0;
__device__ unsigned int g_count = 0u;

// Process one float4 pair. Element (lane,kk) in group k has
//   t = 4k + (4*lane+kk)/25,  j = (4*lane+kk) % 25  (j fixed per lane/kk).
// Interior contribution to (sx - st):  d - d*(x+t) with d = x-t.
// t==0  (FIRST, 4l+kk < 25):  only +d
// t==299(LAST,  4l+kk >= 75): only -d*(x+t)
template <bool FIRST, bool LAST>
__device__ __forceinline__ void process4(float4 xv, float4 tv, int fourl,
                                         float acc[4], float& rec) {
    const float xa[4] = {xv.x, xv.y, xv.z, xv.w};
    const float ta[4] = {tv.x, tv.y, tv.z, tv.w};
    #pragma unroll
    for (int kk = 0; kk < 4; kk++) {
        const float d  = xa[kk] - ta[kk];
        rec = fmaf(d, d, rec);
        const float xt = xa[kk] + ta[kk];
        float c;
        if (FIRST) {
            c = d;
            if (fourl + kk >= 25) c = fmaf(-d, xt, c);
        } else if (LAST) {
            c = (fourl + kk < 75) ? d : 0.0f;
            c = fmaf(-d, xt, c);
        } else {
            c = fmaf(-d, xt, d);
        }
        acc[kk] += c;
    }
}

__global__ void __launch_bounds__(NTHREADS)
loss_kernel(const float* __restrict__ x, const float* __restrict__ tg,
            float* __restrict__ out) {
    const int warp = threadIdx.x >> 5;
    const int lane = threadIdx.x & 31;
    const int slice = blockIdx.x * WPB + warp;          // < 6144

    const float4* __restrict__ x4 = (const float4*)(x  + (size_t)slice * TJ);
    const float4* __restrict__ t4 = (const float4*)(tg + (size_t)slice * TJ);

    const bool active = (lane < JJ);
    const int fourl = lane * 4;

    float acc[4] = {0.0f, 0.0f, 0.0f, 0.0f};
    float rec = 0.0f;

    const float4 z4 = {0.0f, 0.0f, 0.0f, 0.0f};

    // k = 0 (contains all t==0 elements)
    {
        float4 xv = active ? __ldg(x4 + lane) : z4;
        float4 tv = active ? __ldg(t4 + lane) : z4;
        process4<true, false>(xv, tv, fourl, acc, rec);
    }
    // interior groups: t in (0, 299) for every element -> branchless
    #pragma unroll 2
    for (int k = 1; k < KMAX - 1; k++) {
        float4 xv = active ? __ldg(x4 + k * JJ + lane) : z4;
        float4 tv = active ? __ldg(t4 + k * JJ + lane) : z4;
        process4<false, false>(xv, tv, fourl, acc, rec);
    }
    // k = 74 (contains all t==299 elements)
    {
        float4 xv = active ? __ldg(x4 + (KMAX - 1) * JJ + lane) : z4;
        float4 tv = active ? __ldg(t4 + (KMAX - 1) * JJ + lane) : z4;
        process4<false, true>(xv, tv, fourl, acc, rec);
    }

    // rec: full-warp shuffle reduce.
    #pragma unroll
    for (int o = 16; o > 0; o >>= 1)
        rec += __shfl_xor_sync(0xffffffffu, rec, o);

    // Smooth: fold the 100 (lane,kk) accumulators into per-joint sums.
    // (4*lane+kk) for lane<25 is a bijection onto 0..99 -> each joint hit 4x.
    __shared__ float sj[WPB][JJ];
    if (active) sj[warp][lane] = 0.0f;
    __syncwarp();
    if (active) {
        #pragma unroll
        for (int kk = 0; kk < 4; kk++) {
            const int v = fourl + kk;
            const int j = (v >= 75) ? v - 75 : (v >= 50) ? v - 50
                        : (v >= 25) ? v - 25 : v;
            atomicAdd(&sj[warp][j], acc[kk]);
        }
    }
    __syncwarp();

    float av = (lane < JJ - 1) ? fabsf(sj[warp][lane]) : 0.0f;
    #pragma unroll
    for (int o = 16; o > 0; o >>= 1)
        av += __shfl_xor_sync(0xffffffffu, av, o);

    __shared__ double s_rec[WPB];
    __shared__ double s_sm[WPB];
    if (lane == 0) {
        s_rec[warp] = (double)rec;
        s_sm[warp]  = sqrt((double)av) / (double)TJ;
    }
    __syncthreads();

    if (threadIdx.x == 0) {
        double rtot = 0.0, stot = 0.0;
        #pragma unroll
        for (int w = 0; w < WPB; w++) { rtot += s_rec[w]; stot += s_sm[w]; }
        atomicAdd(&g_rec, rtot);
        atomicAdd(&g_smooth, stot);
        __threadfence();
        const unsigned int ticket = atomicAdd(&g_count, 1u);
        if (ticket == NBLK - 1) {
            const double rec_sum = atomicAdd(&g_rec, 0.0);
            const double sm_sum  = atomicAdd(&g_smooth, 0.0);
            const double rec_mean    = rec_sum / ((double)BB * CC * TT * JJ);
            const double smooth_mean = sm_sum  / ((double)BB * CC);
            out[0] = (float)(2.0 * rec_mean + 3.0 * smooth_mean);
            g_rec = 0.0;
            g_smooth = 0.0;
            __threadfence();
            g_count = 0u;
        }
    }
}

extern "C" void kernel_launch(void* const* d_in, const int* in_sizes, int n_in,
                              void* d_out, int out_size) {
    const float* x  = (const float*)d_in[0];
    const float* tg = (const float*)d_in[1];
    float* out = (float*)d_out;

    loss_kernel<<<NBLK, NTHREADS>>>(x, tg, out);
}